// round 11
// baseline (speedup 1.0000x reference)
#include <cuda_runtime.h>
#include <cuda_bf16.h>
#include <math.h>
#include <stdint.h>

// ---------------------------------------------------------------------------
// SupPatchNCELoss — GB300 (sm_103a), round 6
//
// loss = mean_i [ log S1_i - (S2_i - cnt_i) * (1/T) / cnt_i ]
//   S1_i = sum_{j!=i} exp((cos_ij - 1)/T)
//   S2_i = sum_{j!=i, lab_j==lab_i} cos_ij
//   cnt_i = 2*hist[lab_i] - 1
//
// R6 change vs R5: double-buffered cp.async (LDGSTS) pipeline in gram_kernel
// (removes the per-stage LDG latency exposure of the single-buffered loop),
// dynamic smem ring; final reduction widened to 128 blocks.
// ---------------------------------------------------------------------------

#define NPATCH 4096
#define MROWS  8192
#define CDIM   256
#define HSEG   128
#define INV_T  (1.0f / 0.07f)

#define NT 64                        // 8192/128 tiles per dim
#define NPAIRS (NT * (NT + 1) / 2)   // 2080

#define BK 32
#define SKD 36                       // smem k-stride (conflict-free)
#define STAGE_F (128 * SKD)          // floats per tile-buffer

__device__ float g_norm[MROWS * CDIM];
__device__ int   g_lab[NPATCH];
__device__ int   g_hist[8];
__device__ float g_S1p[NT][MROWS];
__device__ float g_S2p[NT][MROWS];
__device__ float g_part[128];

// ---------------------------------------------------------------------------
__device__ __forceinline__ float tf32r(float x) {
    float r;
    asm("cvt.rna.tf32.f32 %0, %1;" : "=f"(r) : "f"(x));
    return r;
}

__device__ __forceinline__ void mma_tf32(float c[4], const unsigned a[4],
                                         const unsigned b[2]) {
    asm volatile(
        "mma.sync.aligned.m16n8k8.row.col.f32.tf32.tf32.f32 "
        "{%0,%1,%2,%3}, {%4,%5,%6,%7}, {%8,%9}, {%0,%1,%2,%3};\n"
        : "+f"(c[0]), "+f"(c[1]), "+f"(c[2]), "+f"(c[3])
        : "r"(a[0]), "r"(a[1]), "r"(a[2]), "r"(a[3]), "r"(b[0]), "r"(b[1]));
}

__device__ __forceinline__ void cp16(float* dst_smem, const float* src) {
    unsigned d = (unsigned)__cvta_generic_to_shared(dst_smem);
    asm volatile("cp.async.cg.shared.global [%0], [%1], 16;\n"
                 :: "r"(d), "l"(src));
}
#define CP_COMMIT() asm volatile("cp.async.commit_group;\n" ::: "memory")
#define CP_WAIT(n)  asm volatile("cp.async.wait_group %0;\n" :: "n"(n) : "memory")

// ---------------------------------------------------------------------------
// 1) labels + histogram (single block)
// ---------------------------------------------------------------------------
__global__ void labels_kernel(const int* __restrict__ seg,
                              const int* __restrict__ coords,
                              const int* __restrict__ crw,
                              const int* __restrict__ crh,
                              const int* __restrict__ crd) {
    __shared__ int sh_hist[8];
    int t = threadIdx.x;
    if (t < 8) sh_hist[t] = 0;
    __syncthreads();
    int cw = *crw, ch = *crh, cd = *crd;
    for (int p = t; p < NPATCH; p += blockDim.x) {
        int cx = coords[p * 3 + 0];
        int cy = coords[p * 3 + 1];
        int cz = coords[p * 3 + 2];
        int ix = (cx * HSEG) / cw;
        int iy = (cy * HSEG) / ch;
        int iz = (cz * HSEG) / cd;
        int l = seg[(ix * HSEG + iy) * HSEG + iz];
        g_lab[p] = l;
        atomicAdd(&sh_hist[l & 7], 1);
    }
    __syncthreads();
    if (t < 8) g_hist[t] = sh_hist[t];
}

// ---------------------------------------------------------------------------
// 2) row-normalize + round to tf32: one warp per row
// ---------------------------------------------------------------------------
__global__ void normalize_kernel(const float* __restrict__ f) {
    int warp = (blockIdx.x * blockDim.x + threadIdx.x) >> 5;
    int lane = threadIdx.x & 31;
    if (warp >= MROWS) return;
    const float4* src = (const float4*)(f + (size_t)warp * CDIM);
    float4 v0 = src[lane];
    float4 v1 = src[lane + 32];
    float ss = v0.x * v0.x + v0.y * v0.y + v0.z * v0.z + v0.w * v0.w
             + v1.x * v1.x + v1.y * v1.y + v1.z * v1.z + v1.w * v1.w;
    #pragma unroll
    for (int o = 16; o > 0; o >>= 1)
        ss += __shfl_xor_sync(0xffffffffu, ss, o);
    float inv = rsqrtf(fmaxf(ss, 1e-24f));
    v0.x = tf32r(v0.x * inv); v0.y = tf32r(v0.y * inv);
    v0.z = tf32r(v0.z * inv); v0.w = tf32r(v0.w * inv);
    v1.x = tf32r(v1.x * inv); v1.y = tf32r(v1.y * inv);
    v1.z = tf32r(v1.z * inv); v1.w = tf32r(v1.w * inv);
    float4* dst = (float4*)(g_norm + (size_t)warp * CDIM);
    dst[lane]      = v0;
    dst[lane + 32] = v1;
}

// ---------------------------------------------------------------------------
// 3) symmetric Gram + fused epilogue, double-buffered cp.async pipeline
//    2080 blocks, 256 threads = 8 warps (wy in {0,1}, wx in {0..3}),
//    warp tile 64x32, block tile 128x128, K staged in chunks of 32.
// ---------------------------------------------------------------------------
__global__ __launch_bounds__(256, 2) void gram_kernel() {
    extern __shared__ float dyn[];
    // dyn layout: As[2][128][SKD] then Bs[2][128][SKD]
    float* Abuf = dyn;
    float* Bbuf = dyn + 2 * STAGE_F;
    #define AS(s, r, k) Abuf[(s) * STAGE_F + (r) * SKD + (k)]
    #define BS(s, r, k) Bbuf[(s) * STAGE_F + (r) * SKD + (k)]

    __shared__ int   labR[128], labC[128];
    __shared__ float sR1[4][128], sR2[4][128];
    __shared__ float sC1[2][128], sC2[2][128];

    // linear block -> (I, J) with I <= J
    int b = blockIdx.x;
    int I = 0;
    while (b >= NT - I) { b -= NT - I; I++; }
    int J = I + b;
    int rowBase = I * 128, colBase = J * 128;

    int tid  = threadIdx.x;
    int lane = tid & 31, w = tid >> 5;
    int wy = w >> 2, wx = w & 3;
    int g = lane >> 2, t4 = lane & 3;

    if (tid < 128) labR[tid] = g_lab[(rowBase + tid) & (NPATCH - 1)];
    else           labC[tid - 128] = g_lab[(colBase + tid - 128) & (NPATCH - 1)];

    // per-thread stage-load coordinates (4 x 16B per tile per stage)
    int srow[4], skq[4];
    #pragma unroll
    for (int i = 0; i < 4; i++) {
        int lin = tid + i * 256;
        srow[i] = lin >> 3;
        skq[i]  = (lin & 7) * 4;
    }

    // prefetch stage 0 (kb = 0)
    #pragma unroll
    for (int i = 0; i < 4; i++) {
        cp16(&AS(0, srow[i], skq[i]),
             g_norm + (size_t)(rowBase + srow[i]) * CDIM + skq[i]);
        cp16(&BS(0, srow[i], skq[i]),
             g_norm + (size_t)(colBase + srow[i]) * CDIM + skq[i]);
    }
    CP_COMMIT();

    float acc[4][4][4];
    #pragma unroll
    for (int mi = 0; mi < 4; mi++)
        #pragma unroll
        for (int ni = 0; ni < 4; ni++)
            #pragma unroll
            for (int q = 0; q < 4; q++) acc[mi][ni][q] = 0.0f;

    #pragma unroll 1
    for (int kbi = 0; kbi < CDIM / BK; kbi++) {
        int cur = kbi & 1;
        if (kbi < CDIM / BK - 1) {
            int kb = (kbi + 1) * BK;
            #pragma unroll
            for (int i = 0; i < 4; i++) {
                cp16(&AS(cur ^ 1, srow[i], skq[i]),
                     g_norm + (size_t)(rowBase + srow[i]) * CDIM + kb + skq[i]);
                cp16(&BS(cur ^ 1, srow[i], skq[i]),
                     g_norm + (size_t)(colBase + srow[i]) * CDIM + kb + skq[i]);
            }
            CP_COMMIT();
            CP_WAIT(1);     // stage `cur` complete; next stage may be in flight
        } else {
            CP_WAIT(0);
        }
        __syncthreads();

        #pragma unroll
        for (int kk = 0; kk < BK; kk += 8) {
            unsigned af[4][4], bf[4][2];
            #pragma unroll
            for (int mi = 0; mi < 4; mi++) {
                int r = wy * 64 + mi * 16 + g;
                af[mi][0] = __float_as_uint(AS(cur, r, kk + t4));
                af[mi][1] = __float_as_uint(AS(cur, r + 8, kk + t4));
                af[mi][2] = __float_as_uint(AS(cur, r, kk + t4 + 4));
                af[mi][3] = __float_as_uint(AS(cur, r + 8, kk + t4 + 4));
            }
            #pragma unroll
            for (int ni = 0; ni < 4; ni++) {
                int c = wx * 32 + ni * 8 + g;
                bf[ni][0] = __float_as_uint(BS(cur, c, kk + t4));
                bf[ni][1] = __float_as_uint(BS(cur, c, kk + t4 + 4));
            }
            #pragma unroll
            for (int mi = 0; mi < 4; mi++)
                #pragma unroll
                for (int ni = 0; ni < 4; ni++)
                    mma_tf32(acc[mi][ni], af[mi], bf[ni]);
        }
        __syncthreads();   // compute done before next iter overwrites `cur`
    }

    // ---- fused epilogue: exp-sum + label-masked cos-sum, both sides ----
    float cs1[4][2], cs2[4][2];
    #pragma unroll
    for (int ni = 0; ni < 4; ni++) {
        cs1[ni][0] = 0.f; cs1[ni][1] = 0.f;
        cs2[ni][0] = 0.f; cs2[ni][1] = 0.f;
    }
    bool diag = (I == J);

    #pragma unroll
    for (int mi = 0; mi < 4; mi++) {
        float rs1[2] = {0.f, 0.f}, rs2[2] = {0.f, 0.f};
        int lr0 = wy * 64 + mi * 16 + g;
        int lr1 = lr0 + 8;
        int labr0 = labR[lr0], labr1 = labR[lr1];
        #pragma unroll
        for (int ni = 0; ni < 4; ni++) {
            int lc0 = wx * 32 + ni * 8 + 2 * t4;
            int lc1 = lc0 + 1;
            int labc0 = labC[lc0], labc1 = labC[lc1];
            #pragma unroll
            for (int q = 0; q < 4; q++) {
                int lr = (q & 2) ? lr1 : lr0;
                int lc = (q & 1) ? lc1 : lc0;
                int lbr = (q & 2) ? labr1 : labr0;
                int lbc = (q & 1) ? labc1 : labc0;
                float v = acc[mi][ni][q];
                bool self = diag && (lr == lc);
                float e = __expf((v - 1.0f) * INV_T);
                if (!self) {
                    rs1[(q >> 1)] += e;
                    cs1[ni][(q & 1)] += e;
                    if (lbr == lbc) {
                        rs2[(q >> 1)] += v;
                        cs2[ni][(q & 1)] += v;
                    }
                }
            }
        }
        #pragma unroll
        for (int h = 0; h < 2; h++) {
            float v1 = rs1[h], v2 = rs2[h];
            v1 += __shfl_xor_sync(0xffffffffu, v1, 1);
            v1 += __shfl_xor_sync(0xffffffffu, v1, 2);
            v2 += __shfl_xor_sync(0xffffffffu, v2, 1);
            v2 += __shfl_xor_sync(0xffffffffu, v2, 2);
            if (t4 == 0) {
                int lr = wy * 64 + mi * 16 + h * 8 + g;
                sR1[wx][lr] = v1;
                sR2[wx][lr] = v2;
            }
        }
    }

    #pragma unroll
    for (int ni = 0; ni < 4; ni++) {
        #pragma unroll
        for (int h = 0; h < 2; h++) {
            float v1 = cs1[ni][h], v2 = cs2[ni][h];
            v1 += __shfl_xor_sync(0xffffffffu, v1, 4);
            v1 += __shfl_xor_sync(0xffffffffu, v1, 8);
            v1 += __shfl_xor_sync(0xffffffffu, v1, 16);
            v2 += __shfl_xor_sync(0xffffffffu, v2, 4);
            v2 += __shfl_xor_sync(0xffffffffu, v2, 8);
            v2 += __shfl_xor_sync(0xffffffffu, v2, 16);
            if (g == 0) {
                int lc = wx * 32 + ni * 8 + 2 * t4 + h;
                sC1[wy][lc] = v1;
                sC2[wy][lc] = v2;
            }
        }
    }
    __syncthreads();

    // deterministic partial writes: slot = other tile index
    if (tid < 128) {
        int r = tid;
        g_S1p[J][rowBase + r] = sR1[0][r] + sR1[1][r] + sR1[2][r] + sR1[3][r];
        g_S2p[J][rowBase + r] = sR2[0][r] + sR2[1][r] + sR2[2][r] + sR2[3][r];
    } else if (I < J) {
        int c = tid - 128;
        g_S1p[I][colBase + c] = sC1[0][c] + sC1[1][c];
        g_S2p[I][colBase + c] = sC2[0][c] + sC2[1][c];
    }
    #undef AS
    #undef BS
}

// ---------------------------------------------------------------------------
// 4) final reduction: 128 blocks x 64 threads, 1 row per thread
// ---------------------------------------------------------------------------
__global__ void final1_kernel() {
    __shared__ float sh[64];
    int row = blockIdx.x * 64 + threadIdx.x;
    float S1a = 0.0f, S2a = 0.0f, S1b = 0.0f, S2b = 0.0f;
    #pragma unroll
    for (int s = 0; s < NT; s += 2) {
        S1a += g_S1p[s][row];
        S2a += g_S2p[s][row];
        S1b += g_S1p[s + 1][row];
        S2b += g_S2p[s + 1][row];
    }
    float S1 = S1a + S1b, S2 = S2a + S2b;
    int lb = g_lab[row & (NPATCH - 1)] & 7;
    float cnt = (float)(2 * g_hist[lb] - 1);
    sh[threadIdx.x] = logf(S1) - (S2 - cnt) * (INV_T / cnt);
    __syncthreads();
    for (int o = 32; o > 0; o >>= 1) {
        if (threadIdx.x < o) sh[threadIdx.x] += sh[threadIdx.x + o];
        __syncthreads();
    }
    if (threadIdx.x == 0) g_part[blockIdx.x] = sh[0];
}

__global__ void final2_kernel(float* __restrict__ out) {
    __shared__ float sh[128];
    sh[threadIdx.x] = g_part[threadIdx.x];
    __syncthreads();
    for (int o = 64; o > 0; o >>= 1) {
        if (threadIdx.x < o) sh[threadIdx.x] += sh[threadIdx.x + o];
        __syncthreads();
    }
    if (threadIdx.x == 0) out[0] = sh[0] / (float)MROWS;
}

// ---------------------------------------------------------------------------
extern "C" void kernel_launch(void* const* d_in, const int* in_sizes, int n_in,
                              void* d_out, int out_size) {
    const float* features = (const float*)d_in[0];
    const int*   seg      = (const int*)d_in[1];
    const int*   coords   = (const int*)d_in[2];
    const int*   crw      = (const int*)d_in[3];
    const int*   crh      = (const int*)d_in[4];
    const int*   crd      = (const int*)d_in[5];
    float* out = (float*)d_out;

    const int dynBytes = 4 * STAGE_F * sizeof(float);   // 73728
    static bool attr_set = false;
    if (!attr_set) {
        cudaFuncSetAttribute(gram_kernel,
                             cudaFuncAttributeMaxDynamicSharedMemorySize,
                             dynBytes);
        attr_set = true;
    }

    labels_kernel<<<1, 256>>>(seg, coords, crw, crh, crd);
    normalize_kernel<<<MROWS / 8, 256>>>(features);
    gram_kernel<<<NPAIRS, 256, dynBytes>>>();
    final1_kernel<<<128, 64>>>();
    final2_kernel<<<1, 128>>>(out);
}

// round 12
// speedup vs baseline: 1.4238x; 1.4238x over previous
#include <cuda_runtime.h>
#include <cuda_fp16.h>
#include <cuda_bf16.h>
#include <math.h>
#include <stdint.h>

// ---------------------------------------------------------------------------
// SupPatchNCELoss — GB300 (sm_103a), round 11: fp16 HMMA Gram
//
// loss = mean_i [ log S1_i - (S2_i - cnt_i) * (1/T) / cnt_i ]
//   S1_i = sum_{j!=i} exp((cos_ij - 1)/T)
//   S2_i = sum_{j!=i, lab_j==lab_i} cos_ij
//   cnt_i = 2*hist[lab_i] - 1
//
// R11 vs R6: Gram operands in fp16 (mma.m16n8k16.f16) — halves smem fragment
// traffic, halves L2 tile stream, doubles tensor rate. Accumulator layout is
// identical to the tf32 m16n8k8 path, so the proven fused epilogue and
// deterministic symmetric-pair partials are unchanged. final1 parallelized 4x.
// ---------------------------------------------------------------------------

#define NPATCH 4096
#define MROWS  8192
#define CDIM   256
#define HSEG   128
#define INV_T  (1.0f / 0.07f)

#define NT 64                        // 8192/128 tiles per dim
#define NPAIRS (NT * (NT + 1) / 2)   // 2080

#define BK 32                        // k-chunk (halves) per stage
#define SKDH 40                      // smem k-stride in halves (conflict-free)
#define STAGE_H (128 * SKDH)         // halves per tile-buffer

__device__ __half g_half[MROWS * CDIM];      // fp16 normalized features (4 MB)
__device__ int    g_lab[NPATCH];
__device__ int    g_hist[8];
__device__ float  g_S1p[NT][MROWS];
__device__ float  g_S2p[NT][MROWS];
__device__ float  g_part[128];

// ---------------------------------------------------------------------------
__device__ __forceinline__ void mma_f16(float c[4], const unsigned a[4],
                                        const unsigned b[2]) {
    asm volatile(
        "mma.sync.aligned.m16n8k16.row.col.f32.f16.f16.f32 "
        "{%0,%1,%2,%3}, {%4,%5,%6,%7}, {%8,%9}, {%0,%1,%2,%3};\n"
        : "+f"(c[0]), "+f"(c[1]), "+f"(c[2]), "+f"(c[3])
        : "r"(a[0]), "r"(a[1]), "r"(a[2]), "r"(a[3]), "r"(b[0]), "r"(b[1]));
}

__device__ __forceinline__ void cp16(__half* dst_smem, const __half* src) {
    unsigned d = (unsigned)__cvta_generic_to_shared(dst_smem);
    asm volatile("cp.async.cg.shared.global [%0], [%1], 16;\n"
                 :: "r"(d), "l"(src));
}
#define CP_COMMIT() asm volatile("cp.async.commit_group;\n" ::: "memory")
#define CP_WAIT(n)  asm volatile("cp.async.wait_group %0;\n" :: "n"(n) : "memory")

// ---------------------------------------------------------------------------
// 1) labels + histogram (single block)
// ---------------------------------------------------------------------------
__global__ void labels_kernel(const int* __restrict__ seg,
                              const int* __restrict__ coords,
                              const int* __restrict__ crw,
                              const int* __restrict__ crh,
                              const int* __restrict__ crd) {
    __shared__ int sh_hist[8];
    int t = threadIdx.x;
    if (t < 8) sh_hist[t] = 0;
    __syncthreads();
    int cw = *crw, ch = *crh, cd = *crd;
    for (int p = t; p < NPATCH; p += blockDim.x) {
        int cx = coords[p * 3 + 0];
        int cy = coords[p * 3 + 1];
        int cz = coords[p * 3 + 2];
        int ix = (cx * HSEG) / cw;
        int iy = (cy * HSEG) / ch;
        int iz = (cz * HSEG) / cd;
        int l = seg[(ix * HSEG + iy) * HSEG + iz];
        g_lab[p] = l;
        atomicAdd(&sh_hist[l & 7], 1);
    }
    __syncthreads();
    if (t < 8) g_hist[t] = sh_hist[t];
}

// ---------------------------------------------------------------------------
// 2) row-normalize -> fp16: one warp per row
// ---------------------------------------------------------------------------
__global__ void normalize_kernel(const float* __restrict__ f) {
    int warp = (blockIdx.x * blockDim.x + threadIdx.x) >> 5;
    int lane = threadIdx.x & 31;
    if (warp >= MROWS) return;
    const float4* src = (const float4*)(f + (size_t)warp * CDIM);
    float4 v0 = src[lane];
    float4 v1 = src[lane + 32];
    float ss = v0.x * v0.x + v0.y * v0.y + v0.z * v0.z + v0.w * v0.w
             + v1.x * v1.x + v1.y * v1.y + v1.z * v1.z + v1.w * v1.w;
    #pragma unroll
    for (int o = 16; o > 0; o >>= 1)
        ss += __shfl_xor_sync(0xffffffffu, ss, o);
    float inv = rsqrtf(fmaxf(ss, 1e-24f));
    __half2* dst = (__half2*)(g_half + (size_t)warp * CDIM);
    // v0 covers cols [lane*4, lane*4+4), v1 covers [128+lane*4, ...)
    dst[lane * 2 + 0]  = __floats2half2_rn(v0.x * inv, v0.y * inv);
    dst[lane * 2 + 1]  = __floats2half2_rn(v0.z * inv, v0.w * inv);
    dst[64 + lane * 2 + 0] = __floats2half2_rn(v1.x * inv, v1.y * inv);
    dst[64 + lane * 2 + 1] = __floats2half2_rn(v1.z * inv, v1.w * inv);
}

// ---------------------------------------------------------------------------
// 3) symmetric Gram + fused epilogue, fp16 HMMA, double-buffered cp.async
//    2080 blocks, 256 threads = 8 warps (wy in {0,1}, wx in {0..3}),
//    warp tile 64x32, block tile 128x128, K staged in chunks of 32 halves.
// ---------------------------------------------------------------------------
__global__ __launch_bounds__(256, 2) void gram_kernel() {
    extern __shared__ __half dynh[];
    __half* Abuf = dynh;                       // [2][128][SKDH]
    __half* Bbuf = dynh + 2 * STAGE_H;
    #define AS(s, r, k) Abuf[(s) * STAGE_H + (r) * SKDH + (k)]
    #define BS(s, r, k) Bbuf[(s) * STAGE_H + (r) * SKDH + (k)]

    __shared__ int   labR[128], labC[128];
    __shared__ float sR1[4][128], sR2[4][128];
    __shared__ float sC1[2][128], sC2[2][128];

    // linear block -> (I, J) with I <= J
    int b = blockIdx.x;
    int I = 0;
    while (b >= NT - I) { b -= NT - I; I++; }
    int J = I + b;
    int rowBase = I * 128, colBase = J * 128;

    int tid  = threadIdx.x;
    int lane = tid & 31, w = tid >> 5;
    int wy = w >> 2, wx = w & 3;
    int g = lane >> 2, t4 = lane & 3;

    if (tid < 128) labR[tid] = g_lab[(rowBase + tid) & (NPATCH - 1)];
    else           labC[tid - 128] = g_lab[(colBase + tid - 128) & (NPATCH - 1)];

    // per-thread stage-load coords: 2 x 16B per tile per stage
    // (128 rows x 32 halves = 4 chunks/row, 512 chunks/tile, 256 threads)
    int srow[2], skq[2];
    #pragma unroll
    for (int i = 0; i < 2; i++) {
        int lin = tid + i * 256;          // 0..511
        srow[i] = lin >> 2;               // 0..127
        skq[i]  = (lin & 3) * 8;          // 0,8,16,24 (halves)
    }

    // prefetch stage 0 (kb = 0)
    #pragma unroll
    for (int i = 0; i < 2; i++) {
        cp16(&AS(0, srow[i], skq[i]),
             g_half + (size_t)(rowBase + srow[i]) * CDIM + skq[i]);
        cp16(&BS(0, srow[i], skq[i]),
             g_half + (size_t)(colBase + srow[i]) * CDIM + skq[i]);
    }
    CP_COMMIT();

    float acc[4][4][4];
    #pragma unroll
    for (int mi = 0; mi < 4; mi++)
        #pragma unroll
        for (int ni = 0; ni < 4; ni++)
            #pragma unroll
            for (int q = 0; q < 4; q++) acc[mi][ni][q] = 0.0f;

    #pragma unroll 1
    for (int kbi = 0; kbi < CDIM / BK; kbi++) {
        int cur = kbi & 1;
        if (kbi < CDIM / BK - 1) {
            int kb = (kbi + 1) * BK;
            #pragma unroll
            for (int i = 0; i < 2; i++) {
                cp16(&AS(cur ^ 1, srow[i], skq[i]),
                     g_half + (size_t)(rowBase + srow[i]) * CDIM + kb + skq[i]);
                cp16(&BS(cur ^ 1, srow[i], skq[i]),
                     g_half + (size_t)(colBase + srow[i]) * CDIM + kb + skq[i]);
            }
            CP_COMMIT();
            CP_WAIT(1);
        } else {
            CP_WAIT(0);
        }
        __syncthreads();

        #pragma unroll
        for (int kk = 0; kk < BK; kk += 16) {
            unsigned af[4][4], bf[4][2];
            #pragma unroll
            for (int mi = 0; mi < 4; mi++) {
                int r = wy * 64 + mi * 16 + g;
                af[mi][0] = *(const unsigned*)&AS(cur, r,     kk + t4 * 2);
                af[mi][1] = *(const unsigned*)&AS(cur, r + 8, kk + t4 * 2);
                af[mi][2] = *(const unsigned*)&AS(cur, r,     kk + t4 * 2 + 8);
                af[mi][3] = *(const unsigned*)&AS(cur, r + 8, kk + t4 * 2 + 8);
            }
            #pragma unroll
            for (int ni = 0; ni < 4; ni++) {
                int c = wx * 32 + ni * 8 + g;
                bf[ni][0] = *(const unsigned*)&BS(cur, c, kk + t4 * 2);
                bf[ni][1] = *(const unsigned*)&BS(cur, c, kk + t4 * 2 + 8);
            }
            #pragma unroll
            for (int mi = 0; mi < 4; mi++)
                #pragma unroll
                for (int ni = 0; ni < 4; ni++)
                    mma_f16(acc[mi][ni], af[mi], bf[ni]);
        }
        __syncthreads();
    }

    // ---- fused epilogue: exp-sum + label-masked cos-sum, both sides ----
    // (accumulator layout identical to tf32 m16n8k8 path: rows g/g+8,
    //  cols 2*t4, 2*t4+1)
    float cs1[4][2], cs2[4][2];
    #pragma unroll
    for (int ni = 0; ni < 4; ni++) {
        cs1[ni][0] = 0.f; cs1[ni][1] = 0.f;
        cs2[ni][0] = 0.f; cs2[ni][1] = 0.f;
    }
    bool diag = (I == J);

    #pragma unroll
    for (int mi = 0; mi < 4; mi++) {
        float rs1[2] = {0.f, 0.f}, rs2[2] = {0.f, 0.f};
        int lr0 = wy * 64 + mi * 16 + g;
        int lr1 = lr0 + 8;
        int labr0 = labR[lr0], labr1 = labR[lr1];
        #pragma unroll
        for (int ni = 0; ni < 4; ni++) {
            int lc0 = wx * 32 + ni * 8 + 2 * t4;
            int lc1 = lc0 + 1;
            int labc0 = labC[lc0], labc1 = labC[lc1];
            #pragma unroll
            for (int q = 0; q < 4; q++) {
                int lr = (q & 2) ? lr1 : lr0;
                int lc = (q & 1) ? lc1 : lc0;
                int lbr = (q & 2) ? labr1 : labr0;
                int lbc = (q & 1) ? labc1 : labc0;
                float v = acc[mi][ni][q];
                bool self = diag && (lr == lc);
                float e = __expf((v - 1.0f) * INV_T);
                if (!self) {
                    rs1[(q >> 1)] += e;
                    cs1[ni][(q & 1)] += e;
                    if (lbr == lbc) {
                        rs2[(q >> 1)] += v;
                        cs2[ni][(q & 1)] += v;
                    }
                }
            }
        }
        #pragma unroll
        for (int h = 0; h < 2; h++) {
            float v1 = rs1[h], v2 = rs2[h];
            v1 += __shfl_xor_sync(0xffffffffu, v1, 1);
            v1 += __shfl_xor_sync(0xffffffffu, v1, 2);
            v2 += __shfl_xor_sync(0xffffffffu, v2, 1);
            v2 += __shfl_xor_sync(0xffffffffu, v2, 2);
            if (t4 == 0) {
                int lr = wy * 64 + mi * 16 + h * 8 + g;
                sR1[wx][lr] = v1;
                sR2[wx][lr] = v2;
            }
        }
    }

    #pragma unroll
    for (int ni = 0; ni < 4; ni++) {
        #pragma unroll
        for (int h = 0; h < 2; h++) {
            float v1 = cs1[ni][h], v2 = cs2[ni][h];
            v1 += __shfl_xor_sync(0xffffffffu, v1, 4);
            v1 += __shfl_xor_sync(0xffffffffu, v1, 8);
            v1 += __shfl_xor_sync(0xffffffffu, v1, 16);
            v2 += __shfl_xor_sync(0xffffffffu, v2, 4);
            v2 += __shfl_xor_sync(0xffffffffu, v2, 8);
            v2 += __shfl_xor_sync(0xffffffffu, v2, 16);
            if (g == 0) {
                int lc = wx * 32 + ni * 8 + 2 * t4 + h;
                sC1[wy][lc] = v1;
                sC2[wy][lc] = v2;
            }
        }
    }
    __syncthreads();

    // deterministic partial writes: slot = other tile index
    if (tid < 128) {
        int r = tid;
        g_S1p[J][rowBase + r] = sR1[0][r] + sR1[1][r] + sR1[2][r] + sR1[3][r];
        g_S2p[J][rowBase + r] = sR2[0][r] + sR2[1][r] + sR2[2][r] + sR2[3][r];
    } else if (I < J) {
        int c = tid - 128;
        g_S1p[I][colBase + c] = sC1[0][c] + sC1[1][c];
        g_S2p[I][colBase + c] = sC2[0][c] + sC2[1][c];
    }
    #undef AS
    #undef BS
}

// ---------------------------------------------------------------------------
// 4) final reduction: 128 blocks x 256 threads; 64 rows/block, 4-way split
//    over the slot dimension per row for 4x load parallelism.
// ---------------------------------------------------------------------------
__global__ void final1_kernel() {
    __shared__ float p1[4][64], p2[4][64];
    __shared__ float sh[64];
    int r6   = threadIdx.x & 63;          // row within block
    int part = threadIdx.x >> 6;          // 0..3 -> slots part*16..+15
    int row  = blockIdx.x * 64 + r6;
    float S1 = 0.0f, S2 = 0.0f;
    #pragma unroll
    for (int s = part * 16; s < part * 16 + 16; s++) {
        S1 += g_S1p[s][row];
        S2 += g_S2p[s][row];
    }
    p1[part][r6] = S1;
    p2[part][r6] = S2;
    __syncthreads();
    if (part == 0) {
        float fS1 = p1[0][r6] + p1[1][r6] + p1[2][r6] + p1[3][r6];
        float fS2 = p2[0][r6] + p2[1][r6] + p2[2][r6] + p2[3][r6];
        int lb = g_lab[row & (NPATCH - 1)] & 7;
        float cnt = (float)(2 * g_hist[lb] - 1);
        sh[r6] = logf(fS1) - (fS2 - cnt) * (INV_T / cnt);
    }
    __syncthreads();
    if (threadIdx.x < 32) {
        float v = sh[threadIdx.x] + sh[threadIdx.x + 32];
        #pragma unroll
        for (int o = 16; o > 0; o >>= 1)
            v += __shfl_xor_sync(0xffffffffu, v, o);
        if (threadIdx.x == 0) g_part[blockIdx.x] = v;
    }
}

__global__ void final2_kernel(float* __restrict__ out) {
    __shared__ float sh[128];
    sh[threadIdx.x] = g_part[threadIdx.x];
    __syncthreads();
    for (int o = 64; o > 0; o >>= 1) {
        if (threadIdx.x < o) sh[threadIdx.x] += sh[threadIdx.x + o];
        __syncthreads();
    }
    if (threadIdx.x == 0) out[0] = sh[0] / (float)MROWS;
}

// ---------------------------------------------------------------------------
extern "C" void kernel_launch(void* const* d_in, const int* in_sizes, int n_in,
                              void* d_out, int out_size) {
    const float* features = (const float*)d_in[0];
    const int*   seg      = (const int*)d_in[1];
    const int*   coords   = (const int*)d_in[2];
    const int*   crw      = (const int*)d_in[3];
    const int*   crh      = (const int*)d_in[4];
    const int*   crd      = (const int*)d_in[5];
    float* out = (float*)d_out;

    const int dynBytes = 4 * STAGE_H * sizeof(__half);   // 40960 < 48K default

    labels_kernel<<<1, 256>>>(seg, coords, crw, crh, crd);
    normalize_kernel<<<MROWS / 8, 256>>>(features);
    gram_kernel<<<NPAIRS, 256, dynBytes>>>();
    final1_kernel<<<128, 256>>>();
    final2_kernel<<<1, 128>>>(out);
}